// round 17
// baseline (speedup 1.0000x reference)
#include <cuda_runtime.h>
#include <cuda_fp16.h>
#include <cstdint>

#define BATCH   2048
#define NTOK    64
#define DIM     256
#define HEADS   8
#define HEADDIM 32
#define MASK_NW 64

// fp16 staging: X, W (q|k|v); Q/K/V scratch in HEAD-MAJOR layout
// [h][b][64][32]; CMB fp32
__device__ __half g_Xh[(size_t)BATCH * NTOK * DIM];
__device__ __half g_Wh[3 * DIM * DIM];
__device__ __half g_Q[(size_t)BATCH * NTOK * DIM];
__device__ __half g_K[(size_t)BATCH * NTOK * DIM];
__device__ __half g_V[(size_t)BATCH * NTOK * DIM];
__device__ float  g_CMB[(size_t)MASK_NW * HEADS * NTOK * NTOK];

__device__ __forceinline__ uint32_t h2bits(float a, float b) {
    __half2 h = __floats2half2_rn(a, b);
    return *(uint32_t*)&h;
}
__device__ __forceinline__ uint32_t smem_u32(const void* p) {
    return (uint32_t)__cvta_generic_to_shared(p);
}
__device__ __forceinline__ void ldsm_x4(uint32_t* r, uint32_t a) {
    asm volatile("ldmatrix.sync.aligned.m8n8.x4.shared.b16 {%0,%1,%2,%3}, [%4];"
        : "=r"(r[0]), "=r"(r[1]), "=r"(r[2]), "=r"(r[3]) : "r"(a));
}
__device__ __forceinline__ void ldsm_x4t(uint32_t* r, uint32_t a) {
    asm volatile("ldmatrix.sync.aligned.m8n8.x4.trans.shared.b16 {%0,%1,%2,%3}, [%4];"
        : "=r"(r[0]), "=r"(r[1]), "=r"(r[2]), "=r"(r[3]) : "r"(a));
}
__device__ __forceinline__ void mma16(float* d, const uint32_t* a, const uint32_t* b) {
    asm("mma.sync.aligned.m16n8k16.row.col.f32.f16.f16.f32 "
        "{%0,%1,%2,%3}, {%4,%5,%6,%7}, {%8,%9}, {%0,%1,%2,%3};"
        : "+f"(d[0]), "+f"(d[1]), "+f"(d[2]), "+f"(d[3])
        : "r"(a[0]), "r"(a[1]), "r"(a[2]), "r"(a[3]), "r"(b[0]), "r"(b[1]));
}
__device__ __forceinline__ void cp16(uint32_t dst, const void* src) {
    asm volatile("cp.async.cg.shared.global [%0], [%1], 16;" :: "r"(dst), "l"(src));
}
__device__ __forceinline__ void cp_commit() {
    asm volatile("cp.async.commit_group;");
}
template <int N>
__device__ __forceinline__ void cp_wait() {
    asm volatile("cp.async.wait_group %0;" :: "n"(N));
}

// ---------------------------------------------------------------------------
// Kernel 0: one-shot prep. Blocks [0,16384): X fp32->fp16; [16384,16480): W;
// [16480,24672): combined mask + rel-bias.
// ---------------------------------------------------------------------------
__global__ void prep_all(const float* __restrict__ X,
                         const float* __restrict__ Wq,
                         const float* __restrict__ Wk,
                         const float* __restrict__ Wv,
                         const float* __restrict__ mask,
                         const float* __restrict__ bt,
                         const int*   __restrict__ ri)
{
    const int bid = blockIdx.x;
    if (bid < 16384) {
        const size_t i8 = ((size_t)bid * 256 + threadIdx.x) * 8;
        const float4 a = *(const float4*)(X + i8);
        const float4 b = *(const float4*)(X + i8 + 4);
        uint32_t r[4] = { h2bits(a.x, a.y), h2bits(a.z, a.w),
                          h2bits(b.x, b.y), h2bits(b.z, b.w) };
        *(uint4*)(g_Xh + i8) = *(uint4*)r;
    } else if (bid < 16384 + 96) {
        const int i8 = ((bid - 16384) * 256 + threadIdx.x) * 8;
        const int t3 = i8 >> 16;
        const int off = i8 & 65535;
        const float* src = (t3 == 0) ? Wq : (t3 == 1) ? Wk : Wv;
        const float4 a = *(const float4*)(src + off);
        const float4 b = *(const float4*)(src + off + 4);
        uint32_t r[4] = { h2bits(a.x, a.y), h2bits(a.z, a.w),
                          h2bits(b.x, b.y), h2bits(b.z, b.w) };
        *(uint4*)(g_Wh + i8) = *(uint4*)r;
    } else {
        const int idx = (bid - 16480) * 256 + threadIdx.x;
        const int p = idx & 4095;
        const int h = (idx >> 12) & 7;
        const int w = idx >> 15;
        g_CMB[idx] = mask[w * 4096 + p] + bt[ri[p] * 8 + h];
    }
}

// ---------------------------------------------------------------------------
// Kernel 1: X-resident QKV GEMM, 128 threads / 4 warps, warp tile 64x64.
//   One CTA per 128-row m-block (1024 CTAs); X tile in swizzled smem (once);
//   6 slabs stream weight tiles through a 4-stage cp.async ring. 2 CTA/SM.
//   LDSM duplication: A 2x, B 2x (vs 2x/4x at 8 warps) -> 16 KB/k16 step.
// ---------------------------------------------------------------------------
#define GEMM_SMEM (128 * 256 * 2 + 4 * 128 * 40 * 2)   // 106496 B

__global__ __launch_bounds__(128, 2) void qkv_gemm_tc(
    const float* __restrict__ Bq, const float* __restrict__ Bk,
    const float* __restrict__ Bv)
{
    extern __shared__ __half sm[];
    __half* Xs  = sm;                 // 128 x 256, swizzled, 512 B rows
    __half* Bsm = sm + 128 * 256;     // 4 stages x 128 x 40

    const int tid  = threadIdx.x;
    const int m0   = blockIdx.x * 128;
    const int lane = tid & 31;
    const int warp = tid >> 5;
    const int g  = lane >> 2;
    const int tg = lane & 3;
    const int wm = (warp >> 1) * 64;   // 2 m-halves
    const int wn = (warp & 1) * 64;    // 2 n-halves

    const uint32_t XsB = smem_u32(Xs);
    const uint32_t BsB = smem_u32(Bsm);
    constexpr uint32_t BSTG = 128 * 40 * 2;

    // ---- one-time X tile load (swizzled): thread = one row ----
    {
        const __half* xsrc = g_Xh + (size_t)(m0 + tid) * DIM;
        const uint32_t rbase = XsB + tid * 512;
        const int sw = (tid & 7) << 4;
        #pragma unroll
        for (int i = 0; i < 32; i++)
            cp16(rbase + ((i * 16) ^ sw), xsrc + i * 8);
        cp_commit();   // group 0
    }

    // ---- B stage load: thread = one row (64 B = 4 cp16) ----
    const uint32_t bdst = BsB + tid * 80;

    auto bsrc = [&](int it) -> const __half* {
        const int nsel = it >> 3, kt = it & 7;
        const int t3 = nsel >> 1, nl0 = (nsel & 1) << 7;
        return g_Wh + t3 * 65536 + (size_t)(nl0 + tid) * 256 + kt * 32;
    };

    #pragma unroll
    for (int p = 0; p < 3; p++) {          // groups 1,2,3
        const __half* sp = bsrc(p);
        #pragma unroll
        for (int j = 0; j < 4; j++)
            cp16(bdst + p * BSTG + j * 16, sp + j * 8);
        cp_commit();
    }

    // ---- ldmatrix lane addresses ----
    const int ra = (lane & 7) + ((lane >> 3) & 1) * 8;
    const int cab = (lane >> 4) * 16;       // bytes (0 or 16)
    uint32_t aArow[4]; int aAsw[4];
    #pragma unroll
    for (int mt = 0; mt < 4; mt++) {
        const int rr = wm + mt * 16 + ra;
        aArow[mt] = XsB + rr * 512;
        aAsw[mt]  = (rr & 7) << 4;
    }
    const int nb = (lane & 7) + (lane >> 4) * 8;
    const int kb = ((lane >> 3) & 1) * 8;
    const uint32_t aB = BsB + ((wn + nb) * 40 + kb) * 2;

    float acc[4][8][4] = {};

    for (int nsel = 0; nsel < 6; nsel++) {
        #pragma unroll
        for (int kt = 0; kt < 8; kt++) {
            const int it = nsel * 8 + kt;
            cp_wait<2>();
            __syncthreads();

            if (it + 3 < 48) {
                const uint32_t sn = ((it + 3) & 3) * BSTG;
                const __half* s3 = bsrc(it + 3);
                #pragma unroll
                for (int j = 0; j < 4; j++)
                    cp16(bdst + sn + j * 16, s3 + j * 8);
            }
            cp_commit();

            const uint32_t s = (it & 3) * BSTG;
            #pragma unroll
            for (int kcb = 0; kcb < 2; kcb++) {
                const int akb = (kt * 32 + kcb * 16) * 2 + cab;
                uint32_t afr[4][4];
                #pragma unroll
                for (int mt = 0; mt < 4; mt++)
                    ldsm_x4(afr[mt], aArow[mt] + (akb ^ aAsw[mt]));
                uint32_t bfr[4][4];
                #pragma unroll
                for (int j = 0; j < 4; j++)
                    ldsm_x4(bfr[j], aB + s + j * 1280 + kcb * 32);
                #pragma unroll
                for (int mt = 0; mt < 4; mt++)
                    #pragma unroll
                    for (int nt = 0; nt < 8; nt++)
                        mma16(acc[mt][nt], afr[mt], &bfr[nt >> 1][(nt & 1) * 2]);
            }
        }

        // ---- slab epilogue: bias add + HEAD-MAJOR store, reset acc ----
        {
            const int t3  = nsel >> 1;
            const int nl0 = (nsel & 1) << 7;
            const float* bias = (t3 == 0) ? Bq : (t3 == 1) ? Bk : Bv;
            __half* outp      = (t3 == 0) ? g_Q : (t3 == 1) ? g_K : g_V;
            #pragma unroll
            for (int nt = 0; nt < 8; nt++) {
                const int c = nl0 + wn + nt * 8 + tg * 2;
                const float b0 = bias[c], b1 = bias[c + 1];
                const size_t hbase = (size_t)(c >> 5) * (BATCH * NTOK) * HEADDIM
                                   + (c & 31);
                #pragma unroll
                for (int mt = 0; mt < 4; mt++) {
                    const int r = m0 + wm + mt * 16 + g;
                    *(uint32_t*)(outp + hbase + (size_t)r * HEADDIM) =
                        h2bits(acc[mt][nt][0] + b0, acc[mt][nt][1] + b1);
                    *(uint32_t*)(outp + hbase + (size_t)(r + 8) * HEADDIM) =
                        h2bits(acc[mt][nt][2] + b0, acc[mt][nt][3] + b1);
                    acc[mt][nt][0] = 0.f; acc[mt][nt][1] = 0.f;
                    acc[mt][nt][2] = 0.f; acc[mt][nt][3] = 0.f;
                }
            }
        }
    }
}

// ---------------------------------------------------------------------------
// Kernel 2: window-batched fp16 attention (verified), dense head-major QKV.
// ---------------------------------------------------------------------------
__global__ __launch_bounds__(128) void attn_tc(float* __restrict__ out)
{
    __shared__ float  cmbs[4096];
    __shared__ __half qkv[2][3][64 * 40];

    const int w   = blockIdx.x;
    const int h   = blockIdx.y;
    const int grp = blockIdx.z;
    const int tid  = threadIdx.x;
    const int lane = tid & 31;
    const int warp = tid >> 5;
    const int g  = lane >> 2;
    const int tg = lane & 3;

    {
        const float* cmb_g = g_CMB + (((size_t)w * HEADS + h) << 12);
        #pragma unroll
        for (int i = 0; i < 8; i++)
            ((float4*)cmbs)[tid + i * 128] = ((const float4*)cmb_g)[tid + i * 128];
    }

    const int r  = tid >> 1;
    const int ch = (tid & 1) * 16;
    const uint32_t qkvB = smem_u32(&qkv[0][0][0]);
    constexpr uint32_t TBUF = 3 * 64 * 40 * 2;
    constexpr uint32_t TTEN = 64 * 40 * 2;
    const uint32_t ldst = (r * 40 + ch) * 2;
    const size_t hoff = (size_t)h * (BATCH * NTOK) * HEADDIM;

    auto qkv_load = [&](int i, int buf) {
        const int b = w + 64 * (grp * 8 + i);
        const size_t go = hoff + ((size_t)b * NTOK + r) * HEADDIM + ch;
        const uint32_t d = qkvB + buf * TBUF + ldst;
        cp16(d,                 g_Q + go);
        cp16(d + 16,            g_Q + go + 8);
        cp16(d + TTEN,          g_K + go);
        cp16(d + TTEN + 16,     g_K + go + 8);
        cp16(d + 2 * TTEN,      g_V + go);
        cp16(d + 2 * TTEN + 16, g_V + go + 8);
    };

    qkv_load(0, 0);
    cp_commit();

    const int ra = (lane & 7) + ((lane >> 3) & 1) * 8;
    const int ca = (lane >> 4) * 8;
    const uint32_t oQ = ((warp * 16 + ra) * 40 + ca) * 2;
    const int nb = (lane & 7) + (lane >> 4) * 8;
    const int kb = ((lane >> 3) & 1) * 8;
    const uint32_t oK = TTEN + (nb * 40 + kb) * 2;
    const uint32_t oV = 2 * TTEN + (ra * 40 + ca) * 2;

    const float scale = 0.17677669529663687f;
    const int r0 = warp * 16 + g;

    for (int i = 0; i < 8; i++) {
        cp_wait<0>();
        __syncthreads();

        if (i < 7) qkv_load(i + 1, (i + 1) & 1);
        cp_commit();

        const uint32_t base = qkvB + (i & 1) * TBUF;
        const uint32_t aQ = base + oQ;
        const uint32_t aK = base + oK;
        const uint32_t aV = base + oV;

        float sacc[8][4] = {};
        #pragma unroll
        for (int kc = 0; kc < HEADDIM; kc += 16) {
            uint32_t afr[4];
            ldsm_x4(afr, aQ + kc * 2);
            #pragma unroll
            for (int j = 0; j < 4; j++) {
                uint32_t bfr[4];
                ldsm_x4(bfr, aK + j * 16 * 80 + kc * 2);
                mma16(sacc[j * 2],     afr, &bfr[0]);
                mma16(sacc[j * 2 + 1], afr, &bfr[2]);
            }
        }

        float v0[16], v1[16];
        #pragma unroll
        for (int nt = 0; nt < 8; nt++) {
            const int c0 = nt * 8 + tg * 2;
            const float2 m0v = *(const float2*)&cmbs[r0 * 64 + c0];
            const float2 m1v = *(const float2*)&cmbs[(r0 + 8) * 64 + c0];
            v0[nt * 2]     = sacc[nt][0] * scale + m0v.x;
            v0[nt * 2 + 1] = sacc[nt][1] * scale + m0v.y;
            v1[nt * 2]     = sacc[nt][2] * scale + m1v.x;
            v1[nt * 2 + 1] = sacc[nt][3] * scale + m1v.y;
        }

        {
            float mx0 = v0[0], mx1 = v1[0];
            #pragma unroll
            for (int j = 1; j < 16; j++) { mx0 = fmaxf(mx0, v0[j]); mx1 = fmaxf(mx1, v1[j]); }
            mx0 = fmaxf(mx0, __shfl_xor_sync(0xffffffffu, mx0, 1));
            mx0 = fmaxf(mx0, __shfl_xor_sync(0xffffffffu, mx0, 2));
            mx1 = fmaxf(mx1, __shfl_xor_sync(0xffffffffu, mx1, 1));
            mx1 = fmaxf(mx1, __shfl_xor_sync(0xffffffffu, mx1, 2));

            float s0 = 0.f, s1 = 0.f;
            #pragma unroll
            for (int j = 0; j < 16; j++) {
                v0[j] = __expf(v0[j] - mx0); s0 += v0[j];
                v1[j] = __expf(v1[j] - mx1); s1 += v1[j];
            }
            s0 += __shfl_xor_sync(0xffffffffu, s0, 1);
            s0 += __shfl_xor_sync(0xffffffffu, s0, 2);
            s1 += __shfl_xor_sync(0xffffffffu, s1, 1);
            s1 += __shfl_xor_sync(0xffffffffu, s1, 2);
            const float inv0 = 1.0f / s0, inv1 = 1.0f / s1;
            #pragma unroll
            for (int j = 0; j < 16; j++) { v0[j] *= inv0; v1[j] *= inv1; }
        }

        float oacc[4][4] = {};
        #pragma unroll
        for (int kt = 0; kt < 4; kt++) {
            uint32_t afr[4];
            afr[0] = h2bits(v0[4 * kt],     v0[4 * kt + 1]);
            afr[1] = h2bits(v1[4 * kt],     v1[4 * kt + 1]);
            afr[2] = h2bits(v0[4 * kt + 2], v0[4 * kt + 3]);
            afr[3] = h2bits(v1[4 * kt + 2], v1[4 * kt + 3]);
            #pragma unroll
            for (int p = 0; p < 2; p++) {
                uint32_t bfr[4];
                ldsm_x4t(bfr, aV + kt * 16 * 80 + p * 32);
                mma16(oacc[p * 2],     afr, &bfr[0]);
                mma16(oacc[p * 2 + 1], afr, &bfr[2]);
            }
        }

        {
            const int b = w + 64 * (grp * 8 + i);
            float* ob = out + (size_t)b * (NTOK * DIM) + h * HEADDIM;
            #pragma unroll
            for (int nt = 0; nt < 4; nt++) {
                const int c0 = nt * 8 + tg * 2;
                *(float2*)(ob + (size_t)r0 * DIM + c0)       = make_float2(oacc[nt][0], oacc[nt][1]);
                *(float2*)(ob + (size_t)(r0 + 8) * DIM + c0) = make_float2(oacc[nt][2], oacc[nt][3]);
            }
        }
    }
}

// ---------------------------------------------------------------------------
extern "C" void kernel_launch(void* const* d_in, const int* in_sizes, int n_in,
                              void* d_out, int out_size)
{
    const float* hs   = (const float*)d_in[0];
    const float* mask = (const float*)d_in[1];
    const float* wq   = (const float*)d_in[2];
    const float* bq   = (const float*)d_in[3];
    const float* wk   = (const float*)d_in[4];
    const float* bk   = (const float*)d_in[5];
    const float* wv   = (const float*)d_in[6];
    const float* bv   = (const float*)d_in[7];
    const float* bt   = (const float*)d_in[8];
    const int*   ri   = (const int*)d_in[9];
    float* out = (float*)d_out;

    static bool attr_set = false;
    if (!attr_set) {
        cudaFuncSetAttribute(qkv_gemm_tc,
                             cudaFuncAttributeMaxDynamicSharedMemorySize, GEMM_SMEM);
        attr_set = true;
    }

    prep_all<<<24672, 256>>>(hs, wq, wk, wv, mask, bt, ri);

    qkv_gemm_tc<<<(BATCH * NTOK) / 128, 128, GEMM_SMEM>>>(bq, bk, bv);

    dim3 attn_grid(MASK_NW, HEADS, 4);
    attn_tc<<<attn_grid, 128>>>(out);
}